// round 4
// baseline (speedup 1.0000x reference)
#include <cuda_runtime.h>
#include <cuda_bf16.h>
#include <cstdint>

// Depth-to-space, SCALE=2 — persistent grid-stride version (single wave).
// in : [B=16, H=128, W=128, C=256] fp32
// out: [B, 2H=256, 2W=256, C/4=64] fp32
// out[b, 2h+j, 2w+k, c] = in[b, h, w, 4c + 2k + j]
//
// Per super-index: 16 consecutive input floats (4x front-batched LDG.128),
// 4x4 component transpose, 4x STG.128 to the four (j,k) positions.
// All accesses 128B-coalesced per warp; .cs streaming hints both sides.
// Grid = exactly one wave (148 SMs x 6 CTAs) -> zero wave transitions,
// no tail wave; loop overlaps next iter's loads with prior stores.

__global__ void __launch_bounds__(256, 6)
d2s_kernel(const float4* __restrict__ in4, float4* __restrict__ out4,
           unsigned total)
{
    unsigned stride = gridDim.x * 256u;

    for (unsigned idx = blockIdx.x * 256u + threadIdx.x; idx < total;
         idx += stride)
    {
        unsigned base4 = idx << 2;

        // Front-batched streaming loads: 64B contiguous per thread
        float4 v0 = __ldcs(in4 + base4 + 0);
        float4 v1 = __ldcs(in4 + base4 + 1);
        float4 v2 = __ldcs(in4 + base4 + 2);
        float4 v3 = __ldcs(in4 + base4 + 3);

        unsigned g     = idx & 15u;          // out channel group 4g..4g+3
        unsigned pixel = idx >> 4;           // b*H*W + h*W + w
        unsigned w     = pixel & 127u;
        unsigned h     = (pixel >> 7) & 127u;
        unsigned b     = pixel >> 14;

        // Output offsets in float4 units:
        // o(j,k) = ((r0+j)<<12) + ((2w+k)<<4) + g
        unsigned r0  = (b << 8) + (h << 1);
        unsigned o00 = (r0 << 12) + (w << 5) + g;
        unsigned o10 = o00 + (1u << 12);
        unsigned o01 = o00 + 16u;
        unsigned o11 = o10 + 16u;

        // s_jk = component (2k+j) of {v0..v3}
        __stcs(out4 + o00, make_float4(v0.x, v1.x, v2.x, v3.x));  // j=0,k=0
        __stcs(out4 + o10, make_float4(v0.y, v1.y, v2.y, v3.y));  // j=1,k=0
        __stcs(out4 + o01, make_float4(v0.z, v1.z, v2.z, v3.z));  // j=0,k=1
        __stcs(out4 + o11, make_float4(v0.w, v1.w, v2.w, v3.w));  // j=1,k=1
    }
}

extern "C" void kernel_launch(void* const* d_in, const int* in_sizes, int n_in,
                              void* d_out, int out_size)
{
    const float4* in4 = (const float4*)d_in[0];
    float4* out4 = (float4*)d_out;

    unsigned total = (unsigned)(in_sizes[0] / 16);   // 4,194,304 super-indices

    // One wave: 148 SMs x 6 CTAs/SM (launch_bounds(256,6))
    unsigned n_blocks = 148u * 6u;

    d2s_kernel<<<n_blocks, 256>>>(in4, out4, total);
}

// round 8
// speedup vs baseline: 1.1172x; 1.1172x over previous
#include <cuda_runtime.h>
#include <cuda_bf16.h>
#include <cstdint>

// Depth-to-space, SCALE=2 — flat launch (best config: MLP4, occ 8).
// in : [B=16, H=128, W=128, C=256] fp32
// out: [B, 2H=256, 2W=256, C/4=64] fp32
// out[b, 2h+j, 2w+k, c] = in[b, h, w, 4c + 2k + j]
//
// Each thread: 16 consecutive input floats (4x front-batched LDG.128.cs,
// 64B contiguous), 4x4 component transpose in registers, 4x STG.128.cs to
// the four (j,k) output positions. Component (2k+j) of loaded float4 m is
// input channel 16g+4m+2k+j = output channel 4g+m at (j,k). Per warp, every
// load and store instruction covers fully-coalesced 128B sectors, and all
// output lines are written in full (no read-for-ownership).

__global__ void __launch_bounds__(256, 8)
d2s_kernel(const float4* __restrict__ in4, float4* __restrict__ out4)
{
    // 16*128*128 pixels * 16 groups = 4,194,304 threads
    unsigned idx = blockIdx.x * 256u + threadIdx.x;

    unsigned g     = idx & 15u;          // out channel group: 4g..4g+3
    unsigned pixel = idx >> 4;           // b*H*W + h*W + w
    unsigned w     = pixel & 127u;
    unsigned h     = (pixel >> 7) & 127u;
    unsigned b     = pixel >> 14;

    // Front-batched streaming loads: 64B contiguous per thread (MLP_p1 = 4)
    unsigned base4 = idx << 2;
    float4 v0 = __ldcs(in4 + base4 + 0);
    float4 v1 = __ldcs(in4 + base4 + 1);
    float4 v2 = __ldcs(in4 + base4 + 2);
    float4 v3 = __ldcs(in4 + base4 + 3);

    // Output offsets in float4 units:
    // o(j,k) = ((r0+j)*256 + 2w+k)*16 + g = ((r0+j)<<12) + ((2w+k)<<4) + g
    unsigned r0  = (b << 8) + (h << 1);            // output row for j=0
    unsigned o00 = (r0 << 12) + (w << 5) + g;
    unsigned o10 = o00 + (1u << 12);               // +1 output row (j=1)
    unsigned o01 = o00 + 16u;                      // +1 output col (k=1)
    unsigned o11 = o10 + 16u;

    // s_jk = component (2k+j) of {v0..v3}
    __stcs(out4 + o00, make_float4(v0.x, v1.x, v2.x, v3.x));  // j=0,k=0
    __stcs(out4 + o10, make_float4(v0.y, v1.y, v2.y, v3.y));  // j=1,k=0
    __stcs(out4 + o01, make_float4(v0.z, v1.z, v2.z, v3.z));  // j=0,k=1
    __stcs(out4 + o11, make_float4(v0.w, v1.w, v2.w, v3.w));  // j=1,k=1
}

extern "C" void kernel_launch(void* const* d_in, const int* in_sizes, int n_in,
                              void* d_out, int out_size)
{
    const float4* in4 = (const float4*)d_in[0];
    float4* out4 = (float4*)d_out;

    // total threads = in_sizes[0] / 16 = 4,194,304
    unsigned n_threads = (unsigned)(in_sizes[0] / 16);
    unsigned n_blocks  = (n_threads + 255u) / 256u;   // 16384

    d2s_kernel<<<n_blocks, 256>>>(in4, out4);
}